// round 10
// baseline (speedup 1.0000x reference)
#include <cuda_runtime.h>
#include <cstdint>

// Graph_Learn: one-kernel triangle scheme with in-grid normalize tail.
// All blocks compute tmpS = exp(relu(sum_f a_f*|xi-xj|)) on a trapezoid
// tile-pair, write direct + mirror to scratch (bitwise-exact symmetry).
// The last 4 finishing blocks of each bt each normalize a 64-row slice
// (row sum == reference column sum by symmetry) scratch -> out, overlapping
// with later-bt compute. No dedicated spinner blocks.

#define Vn 256
#define Fn 64
#define TR 4
#define PAD 68          // floats per smem row (17 * 16B, odd quad stride)

#define SMEM_AS   (Vn * PAD)
#define SMEM_FLOATS (SMEM_AS + Fn)
#define SMEM_BYTES  (SMEM_FLOATS * 4)

typedef unsigned long long u64;

__device__ float g_tmp[32u * Vn * Vn];   // 8 MB scratch (BT <= 32)
__device__ int   g_cnt[32];              // K1-done counters (self-resetting)
__device__ int   g_fin[32];              // tail-done counters (self-resetting)

__device__ __forceinline__ u64 f2add(u64 a, u64 b) {
    u64 d; asm("add.rn.f32x2 %0,%1,%2;" : "=l"(d) : "l"(a), "l"(b)); return d;
}
__device__ __forceinline__ u64 f2fma(u64 a, u64 b, u64 c) {
    u64 d; asm("fma.rn.f32x2 %0,%1,%2,%3;" : "=l"(d) : "l"(a), "l"(b), "l"(c)); return d;
}
__device__ __forceinline__ u64 f2abs(u64 a) {
    u64 d; asm("and.b64 %0,%1,0x7FFFFFFF7FFFFFFF;" : "=l"(d) : "l"(a)); return d;
}
__device__ __forceinline__ u64 packf2(float lo, float hi) {
    u64 d; asm("mov.b64 %0,{%1,%2};" : "=l"(d) : "f"(lo), "f"(hi)); return d;
}
__device__ __forceinline__ void unpackf2(u64 v, float& lo, float& hi) {
    asm("mov.b64 {%0,%1},%2;" : "=f"(lo), "=f"(hi) : "l"(v));
}
__device__ __forceinline__ void lds_2x64(uint32_t addr, u64& p0, u64& p1) {
    asm volatile("ld.shared.v2.u64 {%0,%1},[%2];" : "=l"(p0), "=l"(p1) : "r"(addr));
}
__device__ __forceinline__ int ld_acq(const int* p) {
    int v; asm volatile("ld.acquire.gpu.b32 %0,[%1];" : "=r"(v) : "l"(p) : "memory");
    return v;
}

__device__ __forceinline__ void tile_rows(uint32_t xs_sh, int i0, int f0,
                                          const u64* nxj, const u64* av, u64* acc)
{
    #pragma unroll
    for (int r = 0; r < TR; ++r) {
        const uint32_t base = xs_sh + (uint32_t)(((i0 + r) * PAD + f0) * 4);
        u64 xi[8];
        lds_2x64(base +  0, xi[0], xi[1]);   // uniform broadcast LDS.128
        lds_2x64(base + 16, xi[2], xi[3]);
        lds_2x64(base + 32, xi[4], xi[5]);
        lds_2x64(base + 48, xi[6], xi[7]);
        u64 s = acc[r];
        #pragma unroll
        for (int k = 0; k < 8; ++k) {
            u64 d = f2abs(f2add(xi[k], nxj[k]));   // ADD2 + 2xLOP3
            s = f2fma(d, av[k], s);                // FFMA2
        }
        acc[r] = s;
    }
}

__device__ __forceinline__ void store_tile(const u64* acc, int bt, int i0, int j)
{
    float f[TR];
    #pragma unroll
    for (int r = 0; r < TR; ++r) {
        float lo, hi; unpackf2(acc[r], lo, hi);
        f[r] = __expf(fmaxf(lo + hi, 0.f));
    }
    float* base = g_tmp + ((size_t)bt * Vn + i0) * Vn + j;
    #pragma unroll
    for (int r = 0; r < TR; ++r)
        base[(size_t)r * Vn] = f[r];                      // direct (coalesced)
    // mirror: one aligned float4 per thread -> full 32B sector
    *(float4*)(g_tmp + ((size_t)bt * Vn + j) * Vn + i0) =
        make_float4(f[0], f[1], f[2], f[3]);
}

__global__ __launch_bounds__(256, 3)
void gl_fused(const float* __restrict__ x, const float* __restrict__ a,
              float* __restrict__ out)
{
    extern __shared__ float sm[];
    float* xs  = sm;
    float* as_ = sm + SMEM_AS;
    __shared__ int s_c;

    const int tid = threadIdx.x;
    const int bt  = blockIdx.x >> 5;        // bt-major
    const int k   = blockIdx.x & 31;
    const int iA  = k * TR;
    const int iB  = (Vn - TR) - k * TR;

    // ---- stage x[bt] slice into padded smem ----
    const float4* xp = (const float4*)(x + (size_t)bt * Vn * Fn);
    #pragma unroll
    for (int it = 0; it < 16; ++it) {
        int kk = tid + it * 256;
        float4 v = xp[kk];
        int row = kk >> 4, fc = (kk & 15) << 2;
        *(float4*)&xs[row * PAD + fc] = v;
    }
    if (tid < Fn) as_[tid] = a[tid];
    __syncthreads();

    const int wid  = tid >> 5;
    const int lane = tid & 31;
    const bool actA = ((wid + 1) << 5) > iA;    // warp-uniform
    const bool actB = ((wid + 1) << 5) > iB;

    const uint32_t xs_sh = (uint32_t)__cvta_generic_to_shared(xs);
    const uint32_t as_sh = (uint32_t)__cvta_generic_to_shared(as_);
    const int j = tid;

    u64 accA[TR] = {0,0,0,0}, accB[TR] = {0,0,0,0};

    if (actA | actB) {
        #pragma unroll 1
        for (int c = 0; c < 4; ++c) {
            const int f0 = c << 4;
            u64 nxj[8], av[8];
            {
                const uint32_t jb = xs_sh + (uint32_t)((j * PAD + f0) * 4);
                u64 t[8];
                lds_2x64(jb +  0, t[0], t[1]);
                lds_2x64(jb + 16, t[2], t[3]);
                lds_2x64(jb + 32, t[4], t[5]);
                lds_2x64(jb + 48, t[6], t[7]);
                #pragma unroll
                for (int q = 0; q < 8; ++q) {
                    float lo, hi; unpackf2(t[q], lo, hi);
                    nxj[q] = packf2(-lo, -hi);
                }
                const uint32_t ab = as_sh + (uint32_t)(f0 * 4);
                lds_2x64(ab +  0, av[0], av[1]);
                lds_2x64(ab + 16, av[2], av[3]);
                lds_2x64(ab + 32, av[4], av[5]);
                lds_2x64(ab + 48, av[6], av[7]);
            }
            if (actA) tile_rows(xs_sh, iA, f0, nxj, av, accA);
            if (actB) tile_rows(xs_sh, iB, f0, nxj, av, accB);
        }
    }

    if (actA) store_tile(accA, bt, iA, j);
    if (actB) store_tile(accB, bt, iB, j);

    // ---- release-publish this block's completion, elect tail blocks ----
    __syncthreads();
    if (tid == 0) {
        __threadfence();
        s_c = atomicAdd(&g_cnt[bt], 1);     // old value 0..31
    }
    __syncthreads();
    const int c = s_c;
    if (c < 28) return;                      // not a tail block

    // ---- tail: last 4 blocks normalize 64 rows each ----
    if (tid == 0) {
        while (ld_acq(&g_cnt[bt]) < 32) __nanosleep(32);
    }
    __syncthreads();                         // all 32 blocks' stores visible

    const int slice = c - 28;                // 0..3, disjoint
    const int row0  = slice * 64 + wid * 8;  // 8 rows per warp

    #pragma unroll 1
    for (int b = 0; b < 2; ++b) {            // 2 batches of 4 rows
        const int rb = row0 + b * 4;
        const float4* rp = (const float4*)(g_tmp + ((size_t)bt * Vn + rb) * Vn);
        float4 v[4][2];
        #pragma unroll
        for (int r = 0; r < 4; ++r) {        // 8 front-batched L2 reads
            v[r][0] = __ldcg(rp + (size_t)r * 64 + lane);
            v[r][1] = __ldcg(rp + (size_t)r * 64 + lane + 32);
        }
        float s[4];
        #pragma unroll
        for (int r = 0; r < 4; ++r)
            s[r] = ((v[r][0].x + v[r][0].y) + (v[r][0].z + v[r][0].w))
                 + ((v[r][1].x + v[r][1].y) + (v[r][1].z + v[r][1].w));
        #pragma unroll
        for (int m = 16; m >= 1; m >>= 1) {
            #pragma unroll
            for (int r = 0; r < 4; ++r)
                s[r] += __shfl_xor_sync(0xffffffffu, s[r], m);
        }
        float4* op = (float4*)(out + ((size_t)bt * Vn + rb) * Vn);
        #pragma unroll
        for (int r = 0; r < 4; ++r) {
            const float rc = __fdividef(1.0f, s[r]);
            float4 a0 = v[r][0], a1 = v[r][1];
            a0.x *= rc; a0.y *= rc; a0.z *= rc; a0.w *= rc;
            a1.x *= rc; a1.y *= rc; a1.z *= rc; a1.w *= rc;
            op[(size_t)r * 64 + lane]      = a0;
            op[(size_t)r * 64 + lane + 32] = a1;
        }
    }

    // ---- self-reset counters for next graph replay (handshake) ----
    __syncthreads();
    if (tid == 0) {
        int f = atomicAdd(&g_fin[bt], 1);
        if (f == 3) {                        // last tail block of this bt
            g_cnt[bt] = 0;
            __threadfence();
            g_fin[bt] = 0;
        }
    }
}

extern "C" void kernel_launch(void* const* d_in, const int* in_sizes, int n_in,
                              void* d_out, int out_size)
{
    const float* x = (const float*)d_in[0];
    const float* a = (const float*)d_in[1];
    if (n_in >= 2 && in_sizes[0] == Fn && in_sizes[1] > Fn) {
        x = (const float*)d_in[1];
        a = (const float*)d_in[0];
    }
    int bt = in_sizes[0] == Fn ? in_sizes[1] / (Vn * Fn) : in_sizes[0] / (Vn * Fn);

    cudaFuncSetAttribute(gl_fused, cudaFuncAttributeMaxDynamicSharedMemorySize,
                         SMEM_BYTES);
    gl_fused<<<bt * 32, 256, SMEM_BYTES>>>(x, a, (float*)d_out);
}

// round 11
// speedup vs baseline: 1.1750x; 1.1750x over previous
#include <cuda_runtime.h>
#include <cstdint>

// Graph_Learn fused, packed f32x2, 512-thread row-split blocks.
// S[b,t,i,j] = exp(relu(sum_f a_f*|xi-xj|)) / rowsum
// (row sum == reference column sum by exact bitwise symmetry of tmpS).
// Block covers 8 rows x 256 cols: thread-group h = tid>>8 handles 4 rows,
// j = tid&255 is the column. Halved per-thread state -> 64-reg cap ->
// 2 blocks/SM (32 warps) instead of 3x8=24.

#define Vn 256
#define Fn 64
#define Rr 8            // rows per block
#define HR 4            // rows per thread-group
#define PAD 68          // floats per smem row (17 * 16B, odd quad stride)

#define SMEM_AS   (Vn * PAD)          // a[64] after the slice
#define SMEM_FLOATS (SMEM_AS + Fn)
#define SMEM_BYTES  (SMEM_FLOATS * 4)

typedef unsigned long long u64;

__device__ __forceinline__ u64 f2add(u64 a, u64 b) {
    u64 d; asm("add.rn.f32x2 %0,%1,%2;" : "=l"(d) : "l"(a), "l"(b)); return d;
}
__device__ __forceinline__ u64 f2fma(u64 a, u64 b, u64 c) {
    u64 d; asm("fma.rn.f32x2 %0,%1,%2,%3;" : "=l"(d) : "l"(a), "l"(b), "l"(c)); return d;
}
__device__ __forceinline__ u64 f2abs(u64 a) {
    u64 d; asm("and.b64 %0,%1,0x7FFFFFFF7FFFFFFF;" : "=l"(d) : "l"(a)); return d;
}
__device__ __forceinline__ u64 packf2(float lo, float hi) {
    u64 d; asm("mov.b64 %0,{%1,%2};" : "=l"(d) : "f"(lo), "f"(hi)); return d;
}
__device__ __forceinline__ void unpackf2(u64 v, float& lo, float& hi) {
    asm("mov.b64 {%0,%1},%2;" : "=f"(lo), "=f"(hi) : "l"(v));
}
__device__ __forceinline__ void lds_2x64(uint32_t addr, u64& p0, u64& p1) {
    asm volatile("ld.shared.v2.u64 {%0,%1},[%2];" : "=l"(p0), "=l"(p1) : "r"(addr));
}

__global__ __launch_bounds__(512, 2)
void gl_kernel(const float* __restrict__ x, const float* __restrict__ a,
               float* __restrict__ out)
{
    extern __shared__ float sm[];
    float* xs  = sm;             // [Vn][PAD]
    float* as_ = sm + SMEM_AS;   // a[64]
    __shared__ float wsum[Rr * 8];
    __shared__ float rdn[Rr];

    const int tid = threadIdx.x;
    const int j   = tid & 255;           // column
    const int h   = tid >> 8;            // row-half (0/1)
    const int bt  = blockIdx.y;
    const int i0  = blockIdx.x * Rr + h * HR;   // this group's 4 rows

    // ---- stage x[bt] slice into padded smem (coalesced LDG.128) ----
    const float4* xp = (const float4*)(x + (size_t)bt * Vn * Fn);
    #pragma unroll
    for (int it = 0; it < 8; ++it) {     // 4096 float4 / 512 threads
        int k = tid + it * 512;
        float4 v = xp[k];
        int row = k >> 4;
        int fc  = (k & 15) << 2;
        *(float4*)&xs[row * PAD + fc] = v;
    }
    if (tid < Fn) as_[tid] = a[tid];
    __syncthreads();

    const uint32_t xs_sh = (uint32_t)__cvta_generic_to_shared(xs);
    const uint32_t as_sh = (uint32_t)__cvta_generic_to_shared(as_);

    u64 acc[HR];
    #pragma unroll
    for (int r = 0; r < HR; ++r) acc[r] = 0ull;

    // ---- main: 4 f-chunks of 16 (8 packed pairs per chunk) ----
    #pragma unroll 1
    for (int c = 0; c < 4; ++c) {
        const int f0 = c << 4;
        u64 nxj[8], av[8];
        {
            const uint32_t jb = xs_sh + (uint32_t)((j * PAD + f0) * 4);
            u64 t[8];
            lds_2x64(jb +  0, t[0], t[1]);
            lds_2x64(jb + 16, t[2], t[3]);
            lds_2x64(jb + 32, t[4], t[5]);
            lds_2x64(jb + 48, t[6], t[7]);
            #pragma unroll
            for (int q = 0; q < 8; ++q) {
                float lo, hi; unpackf2(t[q], lo, hi);
                nxj[q] = packf2(-lo, -hi);
            }
            const uint32_t ab = as_sh + (uint32_t)(f0 * 4);
            lds_2x64(ab +  0, av[0], av[1]);
            lds_2x64(ab + 16, av[2], av[3]);
            lds_2x64(ab + 32, av[4], av[5]);
            lds_2x64(ab + 48, av[6], av[7]);
        }
        #pragma unroll
        for (int r = 0; r < HR; ++r) {
            const uint32_t base = xs_sh + (uint32_t)(((i0 + r) * PAD + f0) * 4);
            u64 s = acc[r];
            u64 xi[4];
            // interleave loads/compute: live xi regs stay at 4 u64
            lds_2x64(base +  0, xi[0], xi[1]);
            lds_2x64(base + 16, xi[2], xi[3]);
            #pragma unroll
            for (int k = 0; k < 4; ++k) {
                u64 d = f2abs(f2add(xi[k], nxj[k]));   // ADD2 + 2xLOP3
                s = f2fma(d, av[k], s);                // FFMA2
            }
            lds_2x64(base + 32, xi[0], xi[1]);
            lds_2x64(base + 48, xi[2], xi[3]);
            #pragma unroll
            for (int k = 0; k < 4; ++k) {
                u64 d = f2abs(f2add(xi[k], nxj[4 + k]));
                s = f2fma(d, av[4 + k], s);
            }
            acc[r] = s;
        }
    }

    // ---- tmpS = exp(relu(lo+hi)) ----
    float f[HR];
    #pragma unroll
    for (int r = 0; r < HR; ++r) {
        float lo, hi;
        unpackf2(acc[r], lo, hi);
        f[r] = __expf(fmaxf(lo + hi, 0.f));
    }

    // ---- denom: row sums (== column sums by exact symmetry) ----
    const int lane = tid & 31;
    const int wg   = (tid >> 5) & 7;     // warp within the 256-thread group
    #pragma unroll
    for (int r = 0; r < HR; ++r) {
        float v = f[r];
        v += __shfl_xor_sync(0xffffffffu, v, 16);
        v += __shfl_xor_sync(0xffffffffu, v, 8);
        v += __shfl_xor_sync(0xffffffffu, v, 4);
        v += __shfl_xor_sync(0xffffffffu, v, 2);
        v += __shfl_xor_sync(0xffffffffu, v, 1);
        if (lane == 0) wsum[(h * HR + r) * 8 + wg] = v;
    }
    __syncthreads();
    if (tid < Rr) {
        float d = 0.f;
        #pragma unroll
        for (int q = 0; q < 8; ++q) d += wsum[tid * 8 + q];
        rdn[tid] = __fdividef(1.0f, d);
    }
    __syncthreads();

    // ---- normalize + coalesced store ----
    float* op = out + ((size_t)bt * Vn + i0) * Vn + j;
    #pragma unroll
    for (int r = 0; r < HR; ++r)
        op[(size_t)r * Vn] = f[r] * rdn[h * HR + r];
}

extern "C" void kernel_launch(void* const* d_in, const int* in_sizes, int n_in,
                              void* d_out, int out_size)
{
    const float* x = (const float*)d_in[0];
    const float* a = (const float*)d_in[1];
    if (n_in >= 2 && in_sizes[0] == Fn && in_sizes[1] > Fn) {
        x = (const float*)d_in[1];
        a = (const float*)d_in[0];
    }
    int bt = in_sizes[0] == Fn ? in_sizes[1] / (Vn * Fn) : in_sizes[0] / (Vn * Fn);

    cudaFuncSetAttribute(gl_kernel, cudaFuncAttributeMaxDynamicSharedMemorySize,
                         SMEM_BYTES);
    dim3 grid(Vn / Rr, bt);              // bt slow dim: co-resident blocks share slice
    gl_kernel<<<grid, 512, SMEM_BYTES>>>(x, a, (float*)d_out);
}

// round 12
// speedup vs baseline: 1.2796x; 1.0890x over previous
#include <cuda_runtime.h>
#include <cstdint>

// Graph_Learn fused, packed f32x2, 16 rows/block to amortize xi broadcast LDS.
// S[b,t,i,j] = exp(relu(sum_f a_f*|xi-xj|)) / rowsum
// (row sum == reference column sum by exact bitwise symmetry of tmpS).
// 256 threads (thread = column j), block covers 16 rows: each warp-uniform
// xi LDS wavefront now feeds 16 rows' worth of math -> L1/LDS pressure halved.

#define Vn 256
#define Fn 64
#define Rr 16           // rows per block
#define PAD 68          // floats per smem row (17 * 16B, odd quad stride)

#define SMEM_AS   (Vn * PAD)          // a[64]
#define SMEM_FLOATS (SMEM_AS + Fn)
#define SMEM_BYTES  (SMEM_FLOATS * 4)

typedef unsigned long long u64;

__device__ __forceinline__ u64 f2add(u64 a, u64 b) {
    u64 d; asm("add.rn.f32x2 %0,%1,%2;" : "=l"(d) : "l"(a), "l"(b)); return d;
}
__device__ __forceinline__ u64 f2fma(u64 a, u64 b, u64 c) {
    u64 d; asm("fma.rn.f32x2 %0,%1,%2,%3;" : "=l"(d) : "l"(a), "l"(b), "l"(c)); return d;
}
__device__ __forceinline__ u64 f2abs(u64 a) {
    u64 d; asm("and.b64 %0,%1,0x7FFFFFFF7FFFFFFF;" : "=l"(d) : "l"(a)); return d;
}
__device__ __forceinline__ u64 packf2(float lo, float hi) {
    u64 d; asm("mov.b64 %0,{%1,%2};" : "=l"(d) : "f"(lo), "f"(hi)); return d;
}
__device__ __forceinline__ void unpackf2(u64 v, float& lo, float& hi) {
    asm("mov.b64 {%0,%1},%2;" : "=f"(lo), "=f"(hi) : "l"(v));
}
__device__ __forceinline__ void lds_2x64(uint32_t addr, u64& p0, u64& p1) {
    asm volatile("ld.shared.v2.u64 {%0,%1},[%2];" : "=l"(p0), "=l"(p1) : "r"(addr));
}

__global__ __launch_bounds__(256, 3)
void gl_kernel(const float* __restrict__ x, const float* __restrict__ a,
               float* __restrict__ out)
{
    extern __shared__ float sm[];
    float* xs  = sm;             // [Vn][PAD]
    float* as_ = sm + SMEM_AS;   // a[64]
    __shared__ float wsum[Rr * 8];
    __shared__ float rdn[Rr];

    const int tid = threadIdx.x;
    const int i0  = blockIdx.x * Rr;
    const int bt  = blockIdx.y;
    const int j   = tid;

    // ---- stage x[bt] slice into padded smem (coalesced LDG.128) ----
    const float4* xp = (const float4*)(x + (size_t)bt * Vn * Fn);
    #pragma unroll
    for (int it = 0; it < 16; ++it) {
        int k = tid + it * 256;
        float4 v = xp[k];
        int row = k >> 4;
        int fc  = (k & 15) << 2;
        *(float4*)&xs[row * PAD + fc] = v;
    }
    if (tid < Fn) as_[tid] = a[tid];
    __syncthreads();

    const uint32_t xs_sh = (uint32_t)__cvta_generic_to_shared(xs);
    const uint32_t as_sh = (uint32_t)__cvta_generic_to_shared(as_);

    u64 acc[Rr];
    #pragma unroll
    for (int r = 0; r < Rr; ++r) acc[r] = 0ull;

    // ---- main: 8 f-chunks of 8 floats (4 packed pairs per chunk) ----
    #pragma unroll 1
    for (int c = 0; c < 8; ++c) {
        const int f0 = c << 3;
        u64 nxj[4], av[4];
        {
            const uint32_t jb = xs_sh + (uint32_t)((j * PAD + f0) * 4);
            u64 t[4];
            lds_2x64(jb +  0, t[0], t[1]);
            lds_2x64(jb + 16, t[2], t[3]);
            #pragma unroll
            for (int q = 0; q < 4; ++q) {
                float lo, hi; unpackf2(t[q], lo, hi);
                nxj[q] = packf2(-lo, -hi);
            }
            const uint32_t ab = as_sh + (uint32_t)(f0 * 4);
            lds_2x64(ab + 0, av[0], av[1]);
            lds_2x64(ab + 16, av[2], av[3]);
        }
        #pragma unroll
        for (int r = 0; r < Rr; ++r) {
            const uint32_t base = xs_sh + (uint32_t)(((i0 + r) * PAD + f0) * 4);
            u64 xi[4];
            lds_2x64(base + 0,  xi[0], xi[1]);   // warp-uniform broadcast
            lds_2x64(base + 16, xi[2], xi[3]);
            u64 s = acc[r];
            #pragma unroll
            for (int k = 0; k < 4; ++k) {
                u64 d = f2abs(f2add(xi[k], nxj[k]));   // ADD2 + 2xLOP3
                s = f2fma(d, av[k], s);                // FFMA2
            }
            acc[r] = s;
        }
    }

    // ---- tmpS = exp(relu(lo+hi)) ----
    float f[Rr];
    #pragma unroll
    for (int r = 0; r < Rr; ++r) {
        float lo, hi;
        unpackf2(acc[r], lo, hi);
        f[r] = __expf(fmaxf(lo + hi, 0.f));
    }

    // ---- denom: row sums (== column sums by exact symmetry) ----
    const int lane = tid & 31, w = tid >> 5;
    #pragma unroll
    for (int r = 0; r < Rr; ++r) {
        float v = f[r];
        v += __shfl_xor_sync(0xffffffffu, v, 16);
        v += __shfl_xor_sync(0xffffffffu, v, 8);
        v += __shfl_xor_sync(0xffffffffu, v, 4);
        v += __shfl_xor_sync(0xffffffffu, v, 2);
        v += __shfl_xor_sync(0xffffffffu, v, 1);
        if (lane == 0) wsum[r * 8 + w] = v;
    }
    __syncthreads();
    if (tid < Rr) {
        float d = 0.f;
        #pragma unroll
        for (int q = 0; q < 8; ++q) d += wsum[tid * 8 + q];
        rdn[tid] = __fdividef(1.0f, d);
    }
    __syncthreads();

    // ---- normalize + coalesced store ----
    float* op = out + ((size_t)bt * Vn + i0) * Vn + j;
    #pragma unroll
    for (int r = 0; r < Rr; ++r)
        op[(size_t)r * Vn] = f[r] * rdn[r];
}

extern "C" void kernel_launch(void* const* d_in, const int* in_sizes, int n_in,
                              void* d_out, int out_size)
{
    const float* x = (const float*)d_in[0];
    const float* a = (const float*)d_in[1];
    if (n_in >= 2 && in_sizes[0] == Fn && in_sizes[1] > Fn) {
        x = (const float*)d_in[1];
        a = (const float*)d_in[0];
    }
    int bt = in_sizes[0] == Fn ? in_sizes[1] / (Vn * Fn) : in_sizes[0] / (Vn * Fn);

    cudaFuncSetAttribute(gl_kernel, cudaFuncAttributeMaxDynamicSharedMemorySize,
                         SMEM_BYTES);
    dim3 grid(Vn / Rr, bt);      // bt slow: co-resident blocks share the slice
    gl_kernel<<<grid, 256, SMEM_BYTES>>>(x, a, (float*)d_out);
}